// round 3
// baseline (speedup 1.0000x reference)
#include <cuda_runtime.h>

#define MAXN 50000
#define MAXE 800000
#define FIN  128
#define FHID 128
#define FOUT2 64
#define SCAN_TILE 4096
#define MAXTILES 32

// ---------------- scratch (device globals; no allocation allowed) ----------
__device__ int   g_deg[MAXN];        // in-degree from edges (excl. self loop)
__device__ int   g_off[MAXN + 1];
__device__ int   g_cur[MAXN];
__device__ float g_dis[MAXN];        // rsqrt(deg+1)
__device__ int   g_srcs[MAXE];
__device__ int   g_is64;
__device__ int   g_tsum[MAXTILES];
__device__ float g_xw[MAXN * FHID];  // dis ⊙ (x @ W1)
__device__ float g_h [MAXN * FHID];
__device__ float g_hw[MAXN * FOUT2]; // dis ⊙ (h @ W2)

// ---------------- packed f32x2 helpers -------------------------------------
__device__ __forceinline__ unsigned long long pack2(float lo, float hi) {
    unsigned long long r;
    asm("mov.b64 %0, {%1, %2};" : "=l"(r) : "f"(lo), "f"(hi));
    return r;
}
__device__ __forceinline__ void unpack2(unsigned long long v, float& lo, float& hi) {
    asm("mov.b64 {%0, %1}, %2;" : "=f"(lo), "=f"(hi) : "l"(v));
}
__device__ __forceinline__ void fma2(unsigned long long& d, unsigned long long a,
                                     unsigned long long b) {
    asm("fma.rn.f32x2 %0, %1, %2, %0;" : "+l"(d) : "l"(a), "l"(b));
}

// ---------------- zero + dtype detection -----------------------------------
__global__ void k_zero_detect(const void* ei, int n) {
    int i = blockIdx.x * blockDim.x + threadIdx.x;
    if (i < n) { g_deg[i] = 0; g_cur[i] = 0; }
    if (blockIdx.x == 0) {
        const long long* p = (const long long*)ei;
        int tid = threadIdx.x;
        int ok = 1;
        #pragma unroll
        for (int j = 0; j < 8; j++) {
            long long v = p[tid * 8 + j];
            if (v < 0 || v >= (long long)n) ok = 0;
        }
        int all_ok = __syncthreads_and(ok);
        if (tid == 0) g_is64 = all_ok;
    }
}

__device__ __forceinline__ int load_idx(const void* ei, long long pos, int is64) {
    if (is64) return (int)((const long long*)ei)[pos];
    return ((const int*)ei)[pos];
}

__global__ void k_hist(const void* ei, int E) {
    int e = blockIdx.x * blockDim.x + threadIdx.x;
    if (e >= E) return;
    int is64 = g_is64;
    int col = load_idx(ei, (long long)E + e, is64);
    atomicAdd(&g_deg[col], 1);
}

// ---------------- scan phase 1: per-tile exclusive scan + dis ---------------
__global__ void k_scan1(int n) {
    __shared__ int wsum[32];
    int tid  = threadIdx.x;
    int lane = tid & 31, wid = tid >> 5;
    int base = blockIdx.x * SCAN_TILE + tid * 4;

    int v[4];
    #pragma unroll
    for (int j = 0; j < 4; j++) {
        int i = base + j;
        if (i < n) {
            int d = g_deg[i];
            v[j] = d;
            g_dis[i] = rsqrtf((float)(d + 1));
        } else v[j] = 0;
    }
    int s = v[0] + v[1] + v[2] + v[3];

    int inc = s;
    #pragma unroll
    for (int d = 1; d < 32; d <<= 1) {
        int t = __shfl_up_sync(0xffffffffu, inc, d);
        if (lane >= d) inc += t;
    }
    if (lane == 31) wsum[wid] = inc;
    __syncthreads();
    if (wid == 0) {
        int w = wsum[lane];
        #pragma unroll
        for (int d = 1; d < 32; d <<= 1) {
            int t = __shfl_up_sync(0xffffffffu, w, d);
            if (lane >= d) w += t;
        }
        wsum[lane] = w;
    }
    __syncthreads();
    int excl = inc - s + (wid > 0 ? wsum[wid - 1] : 0);
    int run = excl;
    #pragma unroll
    for (int j = 0; j < 4; j++) {
        int i = base + j;
        if (i < n) g_off[i] = run;
        run += v[j];
    }
    if (tid == 0) g_tsum[blockIdx.x] = wsum[31];
}

// ---------------- scan phases 2+3 merged ------------------------------------
__global__ void k_scan23(int n, int ntiles) {
    __shared__ int sh_toff[32];
    int tid = threadIdx.x;
    if (tid < 32) {
        int t = (tid < ntiles) ? g_tsum[tid] : 0;
        int inc = t;
        #pragma unroll
        for (int d = 1; d < 32; d <<= 1) {
            int u = __shfl_up_sync(0xffffffffu, inc, d);
            if (tid >= d) inc += u;
        }
        sh_toff[tid] = inc - t;
        if (tid == 31 && blockIdx.x == 0) g_off[n] = inc;
    }
    __syncthreads();
    int i = blockIdx.x * blockDim.x + tid;
    if (i < n) g_off[i] += sh_toff[i >> 12];
}

__global__ void k_scatter(const void* ei, int E) {
    int e = blockIdx.x * blockDim.x + threadIdx.x;
    if (e >= E) return;
    int is64 = g_is64;
    int row = load_idx(ei, e, is64);
    int col = load_idx(ei, (long long)E + e, is64);
    int pos = g_off[col] + atomicAdd(&g_cur[col], 1);
    g_srcs[pos] = row;
}

// ---------------- GEMM: Y[n,FO] = scale[r] * (X[n,128] @ W[128,FO]) ---------
// 256 threads; each thread: 8 rows x 8 cols, inner math in packed f32x2.
template <int FO>
__global__ void __launch_bounds__(256, 1)
k_gemm(const float* __restrict__ X, const float* __restrict__ W,
       const float* __restrict__ scale, float* __restrict__ Y, int n) {
    constexpr int NT   = 256;
    constexpr int CGS  = FO / 8;          // col groups of 8 (16 or 8)
    constexpr int RG   = NT / CGS;        // 16 or 32
    constexpr int RPT  = 8;
    constexpr int ROWS = RG * RPT;        // 128 or 256
    constexpr int SXP4 = 33;              // padded float4 row stride
    constexpr int WROW4 = FO / 4;
    extern __shared__ float sh[];
    float4* sW4 = (float4*)sh;                 // 32*FO float4
    float4* sX4 = (float4*)(sh + 128 * FO);    // ROWS * SXP4 float4

    int tid  = threadIdx.x;
    int row0 = blockIdx.x * ROWS;
    const float4* W4g = (const float4*)W;
    const float4* X4g = (const float4*)X;

    for (int i = tid; i < 32 * FO; i += NT) sW4[i] = W4g[i];
    for (int i = tid; i < ROWS * 32; i += NT) {
        int r = i >> 5, c = i & 31;
        int gr = row0 + r;
        sX4[r * SXP4 + c] = (gr < n) ? X4g[gr * 32 + c]
                                     : make_float4(0.f, 0.f, 0.f, 0.f);
    }
    __syncthreads();

    int cg = tid % CGS;                // column group (8 cols)
    int rb = (tid / CGS) * RPT;        // row base within tile
    unsigned long long acc[RPT][4];
    #pragma unroll
    for (int r = 0; r < RPT; r++)
        #pragma unroll
        for (int c = 0; c < 4; c++) acc[r][c] = pack2(0.f, 0.f);

    for (int kk = 0; kk < 32; kk++) {
        unsigned long long wp[4][4];
        #pragma unroll
        for (int k = 0; k < 4; k++) {
            float4 wa = sW4[(4 * kk + k) * WROW4 + cg * 2];
            float4 wb = sW4[(4 * kk + k) * WROW4 + cg * 2 + 1];
            wp[k][0] = pack2(wa.x, wa.y);
            wp[k][1] = pack2(wa.z, wa.w);
            wp[k][2] = pack2(wb.x, wb.y);
            wp[k][3] = pack2(wb.z, wb.w);
        }
        #pragma unroll
        for (int r = 0; r < RPT; r++) {
            float4 a = sX4[(rb + r) * SXP4 + kk];
            unsigned long long a0 = pack2(a.x, a.x);
            unsigned long long a1 = pack2(a.y, a.y);
            unsigned long long a2 = pack2(a.z, a.z);
            unsigned long long a3 = pack2(a.w, a.w);
            #pragma unroll
            for (int c = 0; c < 4; c++) fma2(acc[r][c], a0, wp[0][c]);
            #pragma unroll
            for (int c = 0; c < 4; c++) fma2(acc[r][c], a1, wp[1][c]);
            #pragma unroll
            for (int c = 0; c < 4; c++) fma2(acc[r][c], a2, wp[2][c]);
            #pragma unroll
            for (int c = 0; c < 4; c++) fma2(acc[r][c], a3, wp[3][c]);
        }
    }

    float4* Y4 = (float4*)Y;
    #pragma unroll
    for (int r = 0; r < RPT; r++) {
        int gr = row0 + rb + r;
        if (gr < n) {
            float sc = scale[gr];
            float4 o0, o1;
            unpack2(acc[r][0], o0.x, o0.y); unpack2(acc[r][1], o0.z, o0.w);
            unpack2(acc[r][2], o1.x, o1.y); unpack2(acc[r][3], o1.z, o1.w);
            o0.x *= sc; o0.y *= sc; o0.z *= sc; o0.w *= sc;
            o1.x *= sc; o1.y *= sc; o1.z *= sc; o1.w *= sc;
            Y4[gr * WROW4 + cg * 2]     = o0;
            Y4[gr * WROW4 + cg * 2 + 1] = o1;
        }
    }
}

// ---------------- aggregation: warp per destination node -------------------
// in is pre-scaled by dis: out = di*(sum_{j in in(i)} in[j] + in[i]) + b
__global__ void k_agg128(const float* __restrict__ xw, const float* __restrict__ bias,
                         float* __restrict__ out, int n) {
    int warp = (blockIdx.x * blockDim.x + threadIdx.x) >> 5;
    int lane = threadIdx.x & 31;
    if (warp >= n) return;
    int node = warp;
    int s = g_off[node], e = g_off[node + 1];
    float di = g_dis[node];
    const float4* xw4 = (const float4*)xw;

    float4 acc = xw4[node * 32 + lane];   // self term (pre-scaled)
    int p = s;
    for (; p + 3 < e; p += 4) {
        int s0 = g_srcs[p], s1 = g_srcs[p + 1], s2 = g_srcs[p + 2], s3 = g_srcs[p + 3];
        float4 v0 = xw4[s0 * 32 + lane];
        float4 v1 = xw4[s1 * 32 + lane];
        float4 v2 = xw4[s2 * 32 + lane];
        float4 v3 = xw4[s3 * 32 + lane];
        acc.x += v0.x + v1.x + v2.x + v3.x;
        acc.y += v0.y + v1.y + v2.y + v3.y;
        acc.z += v0.z + v1.z + v2.z + v3.z;
        acc.w += v0.w + v1.w + v2.w + v3.w;
    }
    for (; p < e; p++) {
        int s0 = g_srcs[p];
        float4 v0 = xw4[s0 * 32 + lane];
        acc.x += v0.x; acc.y += v0.y; acc.z += v0.z; acc.w += v0.w;
    }
    float4 bb = ((const float4*)bias)[lane];
    acc.x = fmaxf(di * acc.x + bb.x, 0.f);
    acc.y = fmaxf(di * acc.y + bb.y, 0.f);
    acc.z = fmaxf(di * acc.z + bb.z, 0.f);
    acc.w = fmaxf(di * acc.w + bb.w, 0.f);
    ((float4*)out)[node * 32 + lane] = acc;
}

__global__ void k_agg64(const float* __restrict__ hw, const float* __restrict__ bias,
                        float* __restrict__ out, int n) {
    int warp = (blockIdx.x * blockDim.x + threadIdx.x) >> 5;
    int lane = threadIdx.x & 31;
    if (warp >= n) return;
    int node = warp;
    int s = g_off[node], e = g_off[node + 1];
    float di = g_dis[node];
    const float2* hw2 = (const float2*)hw;

    float2 acc = hw2[node * 32 + lane];   // self term
    int p = s;
    for (; p + 3 < e; p += 4) {
        int s0 = g_srcs[p], s1 = g_srcs[p + 1], s2 = g_srcs[p + 2], s3 = g_srcs[p + 3];
        float2 v0 = hw2[s0 * 32 + lane];
        float2 v1 = hw2[s1 * 32 + lane];
        float2 v2 = hw2[s2 * 32 + lane];
        float2 v3 = hw2[s3 * 32 + lane];
        acc.x += v0.x + v1.x + v2.x + v3.x;
        acc.y += v0.y + v1.y + v2.y + v3.y;
    }
    for (; p < e; p++) {
        int s0 = g_srcs[p];
        float2 v0 = hw2[s0 * 32 + lane];
        acc.x += v0.x; acc.y += v0.y;
    }
    float2 bb = ((const float2*)bias)[lane];
    acc.x = di * acc.x + bb.x;
    acc.y = di * acc.y + bb.y;
    ((float2*)out)[node * 32 + lane] = acc;
}

// ---------------- launch ----------------------------------------------------
extern "C" void kernel_launch(void* const* d_in, const int* in_sizes, int n_in,
                              void* d_out, int out_size) {
    const float* x  = (const float*)d_in[0];
    const void*  ei = d_in[1];
    const float* W1 = (const float*)d_in[2];
    const float* b1 = (const float*)d_in[3];
    const float* W2 = (const float*)d_in[4];
    const float* b2 = (const float*)d_in[5];
    float* out = (float*)d_out;

    int n = in_sizes[0] / FIN;
    int E = in_sizes[1] / 2;
    if (n > MAXN) n = MAXN;
    if (E > MAXE) E = MAXE;
    int ntiles = (n + SCAN_TILE - 1) / SCAN_TILE;

    float *p_xw, *p_h, *p_hw, *p_dis;
    cudaGetSymbolAddress((void**)&p_xw,  g_xw);
    cudaGetSymbolAddress((void**)&p_h,   g_h);
    cudaGetSymbolAddress((void**)&p_hw,  g_hw);
    cudaGetSymbolAddress((void**)&p_dis, g_dis);

    size_t sh128 = (size_t)(128 * 128 + 128 * 132) * sizeof(float);   // 133120
    size_t sh64  = (size_t)(128 * 64  + 256 * 132) * sizeof(float);   // 167936
    cudaFuncSetAttribute(k_gemm<128>, cudaFuncAttributeMaxDynamicSharedMemorySize, (int)sh128);
    cudaFuncSetAttribute(k_gemm<64>,  cudaFuncAttributeMaxDynamicSharedMemorySize, (int)sh64);

    // graph preprocessing (gemm128 slotted at launch index 3 for profiling)
    k_zero_detect<<<(n + 255) / 256, 256>>>(ei, n);                  // 0
    k_hist<<<(E + 255) / 256, 256>>>(ei, E);                         // 1
    k_scan1<<<ntiles, 1024>>>(n);                                    // 2
    k_gemm<128><<<(n + 127) / 128, 256, sh128>>>(x, W1, p_dis, p_xw, n); // 3
    k_scan23<<<(n + 255) / 256, 256>>>(n, ntiles);                   // 4
    k_scatter<<<(E + 255) / 256, 256>>>(ei, E);                      // 5

    // layer 1 aggregate + relu
    k_agg128<<<(n + 7) / 8, 256>>>(p_xw, b1, p_h, n);                // 6

    // layer 2
    k_gemm<64><<<(n + 255) / 256, 256, sh64>>>(p_h, W2, p_dis, p_hw, n); // 7
    k_agg64<<<(n + 7) / 8, 256>>>(p_hw, b2, out, n);                 // 8
}